// round 1
// baseline (speedup 1.0000x reference)
#include <cuda_runtime.h>
#include <cuda_bf16.h>
#include <cstdint>

// Problem constants (fixed by the dataset)
#define NN   2
#define LQn  17821
#define CC   256
#define HDh  8
#define Ll   4
#define Pp   4
#define Dd   32
#define LIN  17821   // sum of level areas: 13400+3350+850+221

// Scratch (device globals; no allocation allowed)
__device__ float g_value[(size_t)NN * LIN * CC];    // value = in_flat @ Wv + bv   [n, lin, hd*D]
__device__ float g_off  [(size_t)NN * LQn * 256];   // offsets logits (pre-reshape) [n, lq, 256]
__device__ float g_att  [(size_t)NN * LQn * 128];   // attention logits             [n, lq, 128]
__device__ float g_mid  [(size_t)NN * LQn * CC];    // sampled output               [n, lq, 256]

// ---------------------------------------------------------------------------
// SGEMM: C[M,N] = A[M,K] @ B[K,N] + bias[N]
// BM=128, BN=64, BK=16, 256 threads, 8x4 per thread. Requires N%64==0, K%16==0.
// ---------------------------------------------------------------------------
#define BM 128
#define BN 64
#define BK 16
#define TM 8
#define TN 4

__global__ __launch_bounds__(256) void sgemm_bias(
    const float* __restrict__ A, const float* __restrict__ B,
    const float* __restrict__ bias, float* __restrict__ C,
    int M, int N, int K)
{
    __shared__ float As[BK][BM];
    __shared__ float Bs[BK][BN];

    const int tid  = threadIdx.x;
    const int row0 = blockIdx.y * BM;
    const int col0 = blockIdx.x * BN;

    // A-tile loading: thread loads float4 at (aRow, aCol) and (aRow+64, aCol)
    const int aRow = tid >> 2;            // 0..63
    const int aCol = (tid & 3) << 2;      // 0,4,8,12
    // B-tile loading: float4 at (bRow, bCol)
    const int bRow = tid >> 4;            // 0..15
    const int bCol = (tid & 15) << 2;     // 0..60

    const int trow = (tid >> 4) * TM;     // 0..120
    const int tcol = (tid & 15) * TN;     // 0..60

    float acc[TM][TN];
#pragma unroll
    for (int i = 0; i < TM; i++)
#pragma unroll
        for (int j = 0; j < TN; j++) acc[i][j] = 0.f;

    for (int k0 = 0; k0 < K; k0 += BK) {
        // load A (with M guard), store transposed
        {
            int r0 = row0 + aRow;
            float4 v0 = make_float4(0.f, 0.f, 0.f, 0.f);
            float4 v1 = make_float4(0.f, 0.f, 0.f, 0.f);
            if (r0 < M)      v0 = *reinterpret_cast<const float4*>(A + (size_t)r0 * K + k0 + aCol);
            if (r0 + 64 < M) v1 = *reinterpret_cast<const float4*>(A + (size_t)(r0 + 64) * K + k0 + aCol);
            As[aCol + 0][aRow] = v0.x;  As[aCol + 1][aRow] = v0.y;
            As[aCol + 2][aRow] = v0.z;  As[aCol + 3][aRow] = v0.w;
            As[aCol + 0][aRow + 64] = v1.x;  As[aCol + 1][aRow + 64] = v1.y;
            As[aCol + 2][aRow + 64] = v1.z;  As[aCol + 3][aRow + 64] = v1.w;
        }
        // load B (N%64==0: no guard)
        {
            float4 v = *reinterpret_cast<const float4*>(B + (size_t)(k0 + bRow) * N + col0 + bCol);
            *reinterpret_cast<float4*>(&Bs[bRow][bCol]) = v;
        }
        __syncthreads();

#pragma unroll
        for (int kk = 0; kk < BK; kk++) {
            float4 a0 = *reinterpret_cast<const float4*>(&As[kk][trow]);
            float4 a1 = *reinterpret_cast<const float4*>(&As[kk][trow + 4]);
            float4 b0 = *reinterpret_cast<const float4*>(&Bs[kk][tcol]);
            float a[TM] = {a0.x, a0.y, a0.z, a0.w, a1.x, a1.y, a1.z, a1.w};
            float b[TN] = {b0.x, b0.y, b0.z, b0.w};
#pragma unroll
            for (int i = 0; i < TM; i++)
#pragma unroll
                for (int j = 0; j < TN; j++)
                    acc[i][j] = fmaf(a[i], b[j], acc[i][j]);
        }
        __syncthreads();
    }

#pragma unroll
    for (int i = 0; i < TM; i++) {
        int r = row0 + trow + i;
        if (r < M) {
#pragma unroll
            for (int j = 0; j < TN; j++) {
                int c = col0 + tcol + j;
                C[(size_t)r * N + c] = acc[i][j] + bias[c];
            }
        }
    }
}

// ---------------------------------------------------------------------------
// Deformable sampling: one warp per (n, lq, hd); lane = channel d (D=32).
//  - softmax over 16 att logits via warp shuffles
//  - bilinear gather from g_value; coalesced 128B per corner per warp
// ---------------------------------------------------------------------------
__global__ __launch_bounds__(256) void msda_sample(
    const float* __restrict__ value,
    const float* __restrict__ off,
    const float* __restrict__ att,
    const float* __restrict__ refp,
    const int*   __restrict__ shapes,
    const int*   __restrict__ starts,
    float* __restrict__ mid)
{
    const int lane = threadIdx.x & 31;
    const int gw   = blockIdx.x * (blockDim.x >> 5) + (threadIdx.x >> 5);
    const int total = NN * LQn * HDh;
    if (gw >= total) return;

    const int n  = gw / (LQn * HDh);
    const int r  = gw - n * (LQn * HDh);
    const int lq = r / HDh;
    const int hd = r - lq * HDh;

    // softmax over the 16 attention logits for this (n, lq, hd)
    const float* attp = att + ((size_t)(n * LQn + lq) * HDh + hd) * 16;
    float logit = (lane < 16) ? attp[lane] : -1e30f;
    float m = logit;
#pragma unroll
    for (int o = 16; o; o >>= 1) m = fmaxf(m, __shfl_xor_sync(0xffffffffu, m, o));
    float e = (lane < 16) ? expf(logit - m) : 0.f;
    float s = e;
#pragma unroll
    for (int o = 16; o; o >>= 1) s += __shfl_xor_sync(0xffffffffu, s, o);
    const float w = e / s;  // valid on lanes 0..15; broadcast via shfl below

    const float* offp = off + ((size_t)(n * LQn + lq) * HDh + hd) * (Ll * Pp * 2);
    const float* rp   = refp + (size_t)(n * LQn + lq) * (Ll * 2);

    float acc = 0.f;
#pragma unroll
    for (int l = 0; l < Ll; l++) {
        const int H  = shapes[l * 2 + 0];
        const int W  = shapes[l * 2 + 1];
        const int s0 = starts[l];
        const float* vb = value + (((size_t)n * LIN + s0) * HDh + hd) * Dd + lane;
        const float rx = rp[l * 2 + 0];
        const float ry = rp[l * 2 + 1];
#pragma unroll
        for (int p = 0; p < Pp; p++) {
            const float ox = offp[l * 8 + p * 2 + 0];
            const float oy = offp[l * 8 + p * 2 + 1];
            const float lx = rx + ox / (float)W;
            const float ly = ry + oy / (float)H;
            const float sx = lx * (float)W - 0.5f;
            const float sy = ly * (float)H - 0.5f;
            const float x0f = floorf(sx), y0f = floorf(sy);
            const int   x0 = (int)x0f,   y0 = (int)y0f;
            const float fx = sx - x0f,   fy = sy - y0f;
            const float aw = __shfl_sync(0xffffffffu, w, l * 4 + p);

            const float w00 = (1.f - fx) * (1.f - fy);
            const float w10 = fx * (1.f - fy);
            const float w01 = (1.f - fx) * fy;
            const float w11 = fx * fy;

            float samp = 0.f;
            const bool xin0 = (x0 >= 0) & (x0 < W);
            const bool xin1 = (x0 + 1 >= 0) & (x0 + 1 < W);
            if (y0 >= 0 && y0 < H) {
                const size_t rowb = (size_t)(y0 * W) * CC;
                if (xin0) samp += w00 * vb[rowb + (size_t)x0 * CC];
                if (xin1) samp += w10 * vb[rowb + (size_t)(x0 + 1) * CC];
            }
            if (y0 + 1 >= 0 && y0 + 1 < H) {
                const size_t rowb = (size_t)((y0 + 1) * W) * CC;
                if (xin0) samp += w01 * vb[rowb + (size_t)x0 * CC];
                if (xin1) samp += w11 * vb[rowb + (size_t)(x0 + 1) * CC];
            }
            acc += aw * samp;
        }
    }

    mid[(((size_t)n * LQn + lq) * HDh + hd) * Dd + lane] = acc;
}

// ---------------------------------------------------------------------------
// Launch
// ---------------------------------------------------------------------------
extern "C" void kernel_launch(void* const* d_in, const int* in_sizes, int n_in,
                              void* d_out, int out_size)
{
    const float* query  = (const float*)d_in[0];
    const float* refp   = (const float*)d_in[1];
    const float* inflat = (const float*)d_in[2];
    const int*   shapes = (const int*)  d_in[3];
    const int*   starts = (const int*)  d_in[4];
    const float* Wv     = (const float*)d_in[5];
    const float* bv     = (const float*)d_in[6];
    const float* Woff   = (const float*)d_in[7];
    const float* boff   = (const float*)d_in[8];
    const float* Watt   = (const float*)d_in[9];
    const float* batt   = (const float*)d_in[10];
    const float* Wout   = (const float*)d_in[11];
    const float* bout   = (const float*)d_in[12];
    float* out = (float*)d_out;

    void *pv, *po, *pa, *pm;
    cudaGetSymbolAddress(&pv, g_value);
    cudaGetSymbolAddress(&po, g_off);
    cudaGetSymbolAddress(&pa, g_att);
    cudaGetSymbolAddress(&pm, g_mid);
    float* gv = (float*)pv;
    float* go = (float*)po;
    float* ga = (float*)pa;
    float* gm = (float*)pm;

    const int M = NN * LQn;           // 35642
    const int Mv = NN * LIN;          // 35642
    dim3 blk(256);

    // 1. value = input_flatten @ Wv + bv   [Mv, 256]
    {
        dim3 grid(CC / BN, (Mv + BM - 1) / BM);
        sgemm_bias<<<grid, blk>>>(inflat, Wv, bv, gv, Mv, CC, CC);
    }
    // 2. offsets = query @ Woff + boff     [M, 256]
    {
        dim3 grid(256 / BN, (M + BM - 1) / BM);
        sgemm_bias<<<grid, blk>>>(query, Woff, boff, go, M, 256, CC);
    }
    // 3. att logits = query @ Watt + batt  [M, 128]
    {
        dim3 grid(128 / BN, (M + BM - 1) / BM);
        sgemm_bias<<<grid, blk>>>(query, Watt, batt, ga, M, 128, CC);
    }
    // 4. deformable sampling -> g_mid
    {
        const int totalWarps = NN * LQn * HDh;       // 285136
        const int warpsPerBlock = 256 / 32;
        dim3 grid((totalWarps + warpsPerBlock - 1) / warpsPerBlock);
        msda_sample<<<grid, blk>>>(gv, go, ga, refp, shapes, starts, gm);
    }
    // 5. out = g_mid @ Wout + bout         [M, 256]
    {
        dim3 grid(CC / BN, (M + BM - 1) / BM);
        sgemm_bias<<<grid, blk>>>(gm, Wout, bout, out, M, CC, CC);
    }
}

// round 2
// speedup vs baseline: 1.5722x; 1.5722x over previous
#include <cuda_runtime.h>
#include <cuda_bf16.h>
#include <cstdint>

// Problem constants (fixed by the dataset)
#define NN   2
#define LQn  17821
#define CC   256
#define HDh  8
#define Ll   4
#define Pp   4
#define Dd   32
#define LIN  17821   // sum of level areas

#define FULLMASK 0xffffffffu

// Scratch (device globals; no allocation allowed)
__device__ float g_value[(size_t)NN * LIN * CC];    // value = in_flat @ Wv + bv   [n, lin, hd*D]
__device__ float g_off  [(size_t)NN * LQn * 256];   // offsets logits               [n, lq, 256]
__device__ float g_att  [(size_t)NN * LQn * 128];   // attention logits             [n, lq, 128]
__device__ float g_mid  [(size_t)NN * LQn * CC];    // sampled output               [n, lq, 256]

// ---------------------------------------------------------------------------
// SGEMM: C[M,N] = A[M,K] @ B[K,N] + bias[N]
// BM=128, BN=64, BK=16, 256 threads, 8x4 per thread. Requires N%64==0, K%16==0.
// ---------------------------------------------------------------------------
#define BM 128
#define BN 64
#define BK 16
#define TM 8
#define TN 4

__global__ __launch_bounds__(256) void sgemm_bias(
    const float* __restrict__ A, const float* __restrict__ B,
    const float* __restrict__ bias, float* __restrict__ C,
    int M, int N, int K)
{
    __shared__ float As[BK][BM];
    __shared__ float Bs[BK][BN];

    const int tid  = threadIdx.x;
    const int row0 = blockIdx.y * BM;
    const int col0 = blockIdx.x * BN;

    const int aRow = tid >> 2;            // 0..63
    const int aCol = (tid & 3) << 2;      // 0,4,8,12
    const int bRow = tid >> 4;            // 0..15
    const int bCol = (tid & 15) << 2;     // 0..60

    const int trow = (tid >> 4) * TM;     // 0..120
    const int tcol = (tid & 15) * TN;     // 0..60

    float acc[TM][TN];
#pragma unroll
    for (int i = 0; i < TM; i++)
#pragma unroll
        for (int j = 0; j < TN; j++) acc[i][j] = 0.f;

    for (int k0 = 0; k0 < K; k0 += BK) {
        {
            int r0 = row0 + aRow;
            float4 v0 = make_float4(0.f, 0.f, 0.f, 0.f);
            float4 v1 = make_float4(0.f, 0.f, 0.f, 0.f);
            if (r0 < M)      v0 = *reinterpret_cast<const float4*>(A + (size_t)r0 * K + k0 + aCol);
            if (r0 + 64 < M) v1 = *reinterpret_cast<const float4*>(A + (size_t)(r0 + 64) * K + k0 + aCol);
            As[aCol + 0][aRow] = v0.x;  As[aCol + 1][aRow] = v0.y;
            As[aCol + 2][aRow] = v0.z;  As[aCol + 3][aRow] = v0.w;
            As[aCol + 0][aRow + 64] = v1.x;  As[aCol + 1][aRow + 64] = v1.y;
            As[aCol + 2][aRow + 64] = v1.z;  As[aCol + 3][aRow + 64] = v1.w;
        }
        {
            float4 v = *reinterpret_cast<const float4*>(B + (size_t)(k0 + bRow) * N + col0 + bCol);
            *reinterpret_cast<float4*>(&Bs[bRow][bCol]) = v;
        }
        __syncthreads();

#pragma unroll
        for (int kk = 0; kk < BK; kk++) {
            float4 a0 = *reinterpret_cast<const float4*>(&As[kk][trow]);
            float4 a1 = *reinterpret_cast<const float4*>(&As[kk][trow + 4]);
            float4 b0 = *reinterpret_cast<const float4*>(&Bs[kk][tcol]);
            float a[TM] = {a0.x, a0.y, a0.z, a0.w, a1.x, a1.y, a1.z, a1.w};
            float b[TN] = {b0.x, b0.y, b0.z, b0.w};
#pragma unroll
            for (int i = 0; i < TM; i++)
#pragma unroll
                for (int j = 0; j < TN; j++)
                    acc[i][j] = fmaf(a[i], b[j], acc[i][j]);
        }
        __syncthreads();
    }

#pragma unroll
    for (int i = 0; i < TM; i++) {
        int r = row0 + trow + i;
        if (r < M) {
#pragma unroll
            for (int j = 0; j < TN; j++) {
                int c = col0 + tcol + j;
                C[(size_t)r * N + c] = acc[i][j] + bias[c];
            }
        }
    }
}

// ---------------------------------------------------------------------------
// Deformable sampling v2: one warp per (n, lq, head-half).
//   lane = g*8 + c :  g in [0,4) = head within half, c in [0,8) = channel quad
//   Each lane accumulates float4 (4 channels) for head hd = half*4+g.
//   Coordinate math parallelized: lane computes corners/weights for its head's
//   points j=c and j=c+8; broadcast within the 8-lane group via width-8 shfl.
//   Boundary handling branch-free: clamp index, zero weight.
// ---------------------------------------------------------------------------
__global__ __launch_bounds__(256) void msda_sample2(
    const float* __restrict__ value,
    const float* __restrict__ off,
    const float* __restrict__ att,
    const float* __restrict__ refp,
    const int*   __restrict__ shapes,
    const int*   __restrict__ starts,
    float* __restrict__ mid)
{
    const int lane = threadIdx.x & 31;
    const int wid  = blockIdx.x * (blockDim.x >> 5) + (threadIdx.x >> 5);
    if (wid >= NN * LQn * 2) return;

    const int nq   = wid >> 1;          // n*LQn + lq  (flat, usable directly)
    const int half = wid & 1;
    const int n    = (nq >= LQn) ? 1 : 0;
    const int g    = lane >> 3;
    const int c    = lane & 7;
    const int hd   = half * 4 + g;

    // --- softmax over 16 logits of head hd; this lane owns j0=c, j1=c+8 ---
    const float* ap = att + ((size_t)nq * HDh + hd) * 16;
    float l0 = ap[c], l1 = ap[c + 8];
    float m = fmaxf(l0, l1);
#pragma unroll
    for (int o = 4; o; o >>= 1) m = fmaxf(m, __shfl_xor_sync(FULLMASK, m, o, 8));
    float e0 = __expf(l0 - m), e1 = __expf(l1 - m);
    float s = e0 + e1;
#pragma unroll
    for (int o = 4; o; o >>= 1) s += __shfl_xor_sync(FULLMASK, s, o, 8);
    const float inv = 1.f / s;
    const float aw0 = e0 * inv, aw1 = e1 * inv;

    // --- per-lane coordinate/weight computation for its 2 points ---
    int   i00[2], i10[2], i01[2], i11[2];
    float w00[2], w10[2], w01[2], w11[2];
    const int nbase = n * LIN;
    const float* op = off + ((size_t)nq * HDh + hd) * 32;

#pragma unroll
    for (int sl = 0; sl < 2; sl++) {
        const int j = c + sl * 8;          // point index 0..15
        const int l = j >> 2;              // level
        const int H  = shapes[2 * l + 0];
        const int W  = shapes[2 * l + 1];
        const int st = starts[l];
        const float rx = refp[((size_t)nq * Ll + l) * 2 + 0];
        const float ry = refp[((size_t)nq * Ll + l) * 2 + 1];
        const float2 o2 = *reinterpret_cast<const float2*>(op + j * 2);
        // (rx + ox/W)*W - 0.5 == rx*W + ox - 0.5
        const float sx = fmaf(rx, (float)W, o2.x) - 0.5f;
        const float sy = fmaf(ry, (float)H, o2.y) - 0.5f;
        const float x0f = floorf(sx), y0f = floorf(sy);
        const int   x0 = (int)x0f,    y0 = (int)y0f;
        const float fx = sx - x0f,    fy = sy - y0f;
        const bool vx0 = (unsigned)x0       < (unsigned)W;
        const bool vx1 = (unsigned)(x0 + 1) < (unsigned)W;
        const bool vy0 = (unsigned)y0       < (unsigned)H;
        const bool vy1 = (unsigned)(y0 + 1) < (unsigned)H;
        const int cx0 = min(max(x0, 0), W - 1);
        const int cx1 = min(max(x0 + 1, 0), W - 1);
        const int cy0 = min(max(y0, 0), H - 1);
        const int cy1 = min(max(y0 + 1, 0), H - 1);
        const int b = nbase + st;
        i00[sl] = b + cy0 * W + cx0;
        i10[sl] = b + cy0 * W + cx1;
        i01[sl] = b + cy1 * W + cx0;
        i11[sl] = b + cy1 * W + cx1;
        const float aw = sl ? aw1 : aw0;
        w00[sl] = (vx0 & vy0) ? (1.f - fx) * (1.f - fy) * aw : 0.f;
        w10[sl] = (vx1 & vy0) ? fx * (1.f - fy) * aw : 0.f;
        w01[sl] = (vx0 & vy1) ? (1.f - fx) * fy * aw : 0.f;
        w11[sl] = (vx1 & vy1) ? fx * fy * aw : 0.f;
    }

    // --- sampling loop: broadcast per point within 8-lane group, float4 gather ---
    const float* vbase = value + hd * Dd + c * 4;
    float4 acc = make_float4(0.f, 0.f, 0.f, 0.f);

#pragma unroll
    for (int j = 0; j < 16; j++) {
        const int sl = j >> 3;
        const int sc = j & 7;
        const int   p00 = __shfl_sync(FULLMASK, i00[sl], sc, 8);
        const int   p10 = __shfl_sync(FULLMASK, i10[sl], sc, 8);
        const int   p01 = __shfl_sync(FULLMASK, i01[sl], sc, 8);
        const int   p11 = __shfl_sync(FULLMASK, i11[sl], sc, 8);
        const float q00 = __shfl_sync(FULLMASK, w00[sl], sc, 8);
        const float q10 = __shfl_sync(FULLMASK, w10[sl], sc, 8);
        const float q01 = __shfl_sync(FULLMASK, w01[sl], sc, 8);
        const float q11 = __shfl_sync(FULLMASK, w11[sl], sc, 8);

        float4 v;
        v = *reinterpret_cast<const float4*>(vbase + (size_t)p00 * CC);
        acc.x = fmaf(q00, v.x, acc.x); acc.y = fmaf(q00, v.y, acc.y);
        acc.z = fmaf(q00, v.z, acc.z); acc.w = fmaf(q00, v.w, acc.w);
        v = *reinterpret_cast<const float4*>(vbase + (size_t)p10 * CC);
        acc.x = fmaf(q10, v.x, acc.x); acc.y = fmaf(q10, v.y, acc.y);
        acc.z = fmaf(q10, v.z, acc.z); acc.w = fmaf(q10, v.w, acc.w);
        v = *reinterpret_cast<const float4*>(vbase + (size_t)p01 * CC);
        acc.x = fmaf(q01, v.x, acc.x); acc.y = fmaf(q01, v.y, acc.y);
        acc.z = fmaf(q01, v.z, acc.z); acc.w = fmaf(q01, v.w, acc.w);
        v = *reinterpret_cast<const float4*>(vbase + (size_t)p11 * CC);
        acc.x = fmaf(q11, v.x, acc.x); acc.y = fmaf(q11, v.y, acc.y);
        acc.z = fmaf(q11, v.z, acc.z); acc.w = fmaf(q11, v.w, acc.w);
    }

    *reinterpret_cast<float4*>(mid + (size_t)nq * CC + hd * Dd + c * 4) = acc;
}

// ---------------------------------------------------------------------------
// Launch
// ---------------------------------------------------------------------------
extern "C" void kernel_launch(void* const* d_in, const int* in_sizes, int n_in,
                              void* d_out, int out_size)
{
    const float* query  = (const float*)d_in[0];
    const float* refp   = (const float*)d_in[1];
    const float* inflat = (const float*)d_in[2];
    const int*   shapes = (const int*)  d_in[3];
    const int*   starts = (const int*)  d_in[4];
    const float* Wv     = (const float*)d_in[5];
    const float* bv     = (const float*)d_in[6];
    const float* Woff   = (const float*)d_in[7];
    const float* boff   = (const float*)d_in[8];
    const float* Watt   = (const float*)d_in[9];
    const float* batt   = (const float*)d_in[10];
    const float* Wout   = (const float*)d_in[11];
    const float* bout   = (const float*)d_in[12];
    float* out = (float*)d_out;

    void *pv, *po, *pa, *pm;
    cudaGetSymbolAddress(&pv, g_value);
    cudaGetSymbolAddress(&po, g_off);
    cudaGetSymbolAddress(&pa, g_att);
    cudaGetSymbolAddress(&pm, g_mid);
    float* gv = (float*)pv;
    float* go = (float*)po;
    float* ga = (float*)pa;
    float* gm = (float*)pm;

    const int M  = NN * LQn;          // 35642
    const int Mv = NN * LIN;          // 35642
    dim3 blk(256);

    // 1. value = input_flatten @ Wv + bv   [Mv, 256]
    {
        dim3 grid(CC / BN, (Mv + BM - 1) / BM);
        sgemm_bias<<<grid, blk>>>(inflat, Wv, bv, gv, Mv, CC, CC);
    }
    // 2. offsets = query @ Woff + boff     [M, 256]
    {
        dim3 grid(256 / BN, (M + BM - 1) / BM);
        sgemm_bias<<<grid, blk>>>(query, Woff, boff, go, M, 256, CC);
    }
    // 3. att logits = query @ Watt + batt  [M, 128]
    {
        dim3 grid(128 / BN, (M + BM - 1) / BM);
        sgemm_bias<<<grid, blk>>>(query, Watt, batt, ga, M, 128, CC);
    }
    // 4. deformable sampling -> g_mid
    {
        const int totalWarps = NN * LQn * 2;          // 71284
        const int warpsPerBlock = 256 / 32;
        dim3 grid((totalWarps + warpsPerBlock - 1) / warpsPerBlock);
        msda_sample2<<<grid, blk>>>(gv, go, ga, refp, shapes, starts, gm);
    }
    // 5. out = g_mid @ Wout + bout         [M, 256]
    {
        dim3 grid(CC / BN, (M + BM - 1) / BM);
        sgemm_bias<<<grid, blk>>>(gm, Wout, bout, out, M, CC, CC);
    }
}

// round 13
// speedup vs baseline: 1.7408x; 1.1072x over previous
#include <cuda_runtime.h>
#include <cuda_bf16.h>
#include <cstdint>

// Problem constants (fixed by the dataset)
#define NN   2
#define LQn  17821
#define CC   256
#define HDh  8
#define Ll   4
#define Pp   4
#define Dd   32
#define LIN  17821

#define FULLMASK 0xffffffffu

// Scratch (device globals; no allocation allowed)
__device__ float g_value[(size_t)NN * LIN * CC];
__device__ float g_off  [(size_t)NN * LQn * 256];
__device__ float g_att  [(size_t)NN * LQn * 128];
__device__ float g_mid  [(size_t)NN * LQn * CC];

// ---------------------------------------------------------------------------
// bf16x3 split-precision GEMM on tensor cores.
//   C[M,N] = A[M,K] @ B[K,N] + bias[N], fp32 in/out, fp32 accuracy ~1e-5.
//   a = hi + lo (bf16 each); C = Ahi*Bhi + Ahi*Blo + Alo*Bhi (drop lo*lo).
//   Block: 256 thr (8 warps), BM=128, BN=128, BK=16. Warp tile 32x64.
//   mma.sync.aligned.m16n8k16.row.col.f32.bf16.bf16.f32
// ---------------------------------------------------------------------------
#define GBM 128
#define GBN 128
#define GBK 16
#define AS_STRIDE 12    // uint32 words per A row (8 k-pairs + 4 pad) -> conflict-free frag LDS
#define BS_STRIDE (GBN + 8)  // 136 words per B k'-row -> conflict-free frag LDS

__device__ __forceinline__ unsigned pack_bf2(__nv_bfloat16 a, __nv_bfloat16 b) {
    __nv_bfloat162 t = __halves2bfloat162(a, b);  // a -> low 16, b -> high 16
    return *reinterpret_cast<unsigned*>(&t);
}

__device__ __forceinline__ void split_f32(float x, __nv_bfloat16& hi, __nv_bfloat16& lo) {
    hi = __float2bfloat16_rn(x);
    lo = __float2bfloat16_rn(x - __bfloat162float(hi));
}

__device__ __forceinline__ void mma_bf16(float* c, const unsigned* a, const unsigned* b) {
    asm volatile(
        "mma.sync.aligned.m16n8k16.row.col.f32.bf16.bf16.f32 "
        "{%0,%1,%2,%3}, {%4,%5,%6,%7}, {%8,%9}, {%0,%1,%2,%3};\n"
        : "+f"(c[0]), "+f"(c[1]), "+f"(c[2]), "+f"(c[3])
        : "r"(a[0]), "r"(a[1]), "r"(a[2]), "r"(a[3]), "r"(b[0]), "r"(b[1]));
}

__global__ __launch_bounds__(256) void gemm_bf16x3(
    const float* __restrict__ A, const float* __restrict__ B,
    const float* __restrict__ bias, float* __restrict__ C,
    int M, int N, int K)
{
    __shared__ unsigned AsH[GBM * AS_STRIDE];
    __shared__ unsigned AsL[GBM * AS_STRIDE];
    __shared__ unsigned BsH[(GBK / 2) * BS_STRIDE];
    __shared__ unsigned BsL[(GBK / 2) * BS_STRIDE];

    const int tid  = threadIdx.x;
    const int lane = tid & 31;
    const int warp = tid >> 5;
    const int g    = lane >> 2;     // 0..7
    const int tig  = lane & 3;      // 0..3
    const int wm   = warp >> 1;     // 0..3 -> m offset 32*wm
    const int wn   = warp & 1;      // 0..1 -> n offset 64*wn

    const int row0 = blockIdx.y * GBM;
    const int col0 = blockIdx.x * GBN;

    // A staging coords: thread -> (row r, k-segment of 8)
    const int ar   = tid >> 1;            // 0..127
    const int acs  = (tid & 1) * 8;       // 0 or 8 (k offset)
    // B staging coords: thread -> (k-pair k2, 4 cols)
    const int bk2  = tid >> 5;            // 0..7
    const int bnw  = (tid & 31) * 4;      // 0..124

    float acc[2][8][4];
#pragma unroll
    for (int i = 0; i < 2; i++)
#pragma unroll
        for (int j = 0; j < 8; j++)
#pragma unroll
            for (int r = 0; r < 4; r++) acc[i][j][r] = 0.f;

    for (int k0 = 0; k0 < K; k0 += GBK) {
        // ---- stage A (128 x 16 fp32 -> hi/lo bf16 pairs) ----
        {
            float4 v0 = make_float4(0.f, 0.f, 0.f, 0.f);
            float4 v1 = make_float4(0.f, 0.f, 0.f, 0.f);
            if (row0 + ar < M) {
                const float* Ap = A + (size_t)(row0 + ar) * K + k0 + acs;
                v0 = *reinterpret_cast<const float4*>(Ap);
                v1 = *reinterpret_cast<const float4*>(Ap + 4);
            }
            __nv_bfloat16 h[8], l[8];
            split_f32(v0.x, h[0], l[0]); split_f32(v0.y, h[1], l[1]);
            split_f32(v0.z, h[2], l[2]); split_f32(v0.w, h[3], l[3]);
            split_f32(v1.x, h[4], l[4]); split_f32(v1.y, h[5], l[5]);
            split_f32(v1.z, h[6], l[6]); split_f32(v1.w, h[7], l[7]);
            uint4 uh = make_uint4(pack_bf2(h[0], h[1]), pack_bf2(h[2], h[3]),
                                  pack_bf2(h[4], h[5]), pack_bf2(h[6], h[7]));
            uint4 ul = make_uint4(pack_bf2(l[0], l[1]), pack_bf2(l[2], l[3]),
                                  pack_bf2(l[4], l[5]), pack_bf2(l[6], l[7]));
            const int w = ar * AS_STRIDE + (acs >> 1);
            *reinterpret_cast<uint4*>(&AsH[w]) = uh;
            *reinterpret_cast<uint4*>(&AsL[w]) = ul;
        }
        // ---- stage B (16 x 128 fp32 -> k-paired hi/lo) ----
        {
            const float* Bp = B + (size_t)(k0 + 2 * bk2) * N + col0 + bnw;
            float4 r0 = *reinterpret_cast<const float4*>(Bp);
            float4 r1 = *reinterpret_cast<const float4*>(Bp + N);
            __nv_bfloat16 h0[4], l0[4], h1[4], l1[4];
            split_f32(r0.x, h0[0], l0[0]); split_f32(r0.y, h0[1], l0[1]);
            split_f32(r0.z, h0[2], l0[2]); split_f32(r0.w, h0[3], l0[3]);
            split_f32(r1.x, h1[0], l1[0]); split_f32(r1.y, h1[1], l1[1]);
            split_f32(r1.z, h1[2], l1[2]); split_f32(r1.w, h1[3], l1[3]);
            uint4 uh = make_uint4(pack_bf2(h0[0], h1[0]), pack_bf2(h0[1], h1[1]),
                                  pack_bf2(h0[2], h1[2]), pack_bf2(h0[3], h1[3]));
            uint4 ul = make_uint4(pack_bf2(l0[0], l1[0]), pack_bf2(l0[1], l1[1]),
                                  pack_bf2(l0[2], l1[2]), pack_bf2(l0[3], l1[3]));
            const int w = bk2 * BS_STRIDE + bnw;
            *reinterpret_cast<uint4*>(&BsH[w]) = uh;
            *reinterpret_cast<uint4*>(&BsL[w]) = ul;
        }
        __syncthreads();

        // ---- fragments + MMA ----
        unsigned aH[2][4], aL[2][4];
#pragma unroll
        for (int i = 0; i < 2; i++) {
            const int r0i = (wm * 32 + i * 16 + g) * AS_STRIDE;
            const int r1i = (wm * 32 + i * 16 + 8 + g) * AS_STRIDE;
            aH[i][0] = AsH[r0i + tig];     aH[i][1] = AsH[r1i + tig];
            aH[i][2] = AsH[r0i + tig + 4]; aH[i][3] = AsH[r1i + tig + 4];
            aL[i][0] = AsL[r0i + tig];     aL[i][1] = AsL[r1i + tig];
            aL[i][2] = AsL[r0i + tig + 4]; aL[i][3] = AsL[r1i + tig + 4];
        }
#pragma unroll
        for (int j = 0; j < 8; j++) {
            const int bc = wn * 64 + j * 8 + g;
            unsigned bH[2], bL[2];
            bH[0] = BsH[tig * BS_STRIDE + bc];
            bH[1] = BsH[(tig + 4) * BS_STRIDE + bc];
            bL[0] = BsL[tig * BS_STRIDE + bc];
            bL[1] = BsL[(tig + 4) * BS_STRIDE + bc];
#pragma unroll
            for (int i = 0; i < 2; i++) {
                mma_bf16(acc[i][j], aH[i], bH);
                mma_bf16(acc[i][j], aH[i], bL);
                mma_bf16(acc[i][j], aL[i], bH);
            }
        }
        __syncthreads();
    }

    // ---- epilogue: add bias, store fp32 ----
#pragma unroll
    for (int i = 0; i < 2; i++) {
#pragma unroll
        for (int j = 0; j < 8; j++) {
            const int col = col0 + wn * 64 + j * 8 + 2 * tig;
            const float b0 = bias[col], b1 = bias[col + 1];
            const int r0i = row0 + wm * 32 + i * 16 + g;
            if (r0i < M) {
                float2 v = make_float2(acc[i][j][0] + b0, acc[i][j][1] + b1);
                *reinterpret_cast<float2*>(C + (size_t)r0i * N + col) = v;
            }
            if (r0i + 8 < M) {
                float2 v = make_float2(acc[i][j][2] + b0, acc[i][j][3] + b1);
                *reinterpret_cast<float2*>(C + (size_t)(r0i + 8) * N + col) = v;
            }
        }
    }
}

// ---------------------------------------------------------------------------
// Deformable sampling (round-2 winner, unchanged): one warp per (n, lq, head-half)
// ---------------------------------------------------------------------------
__global__ __launch_bounds__(256) void msda_sample2(
    const float* __restrict__ value,
    const float* __restrict__ off,
    const float* __restrict__ att,
    const float* __restrict__ refp,
    const int*   __restrict__ shapes,
    const int*   __restrict__ starts,
    float* __restrict__ mid)
{
    const int lane = threadIdx.x & 31;
    const int wid  = blockIdx.x * (blockDim.x >> 5) + (threadIdx.x >> 5);
    if (wid >= NN * LQn * 2) return;

    const int nq   = wid >> 1;
    const int half = wid & 1;
    const int n    = (nq >= LQn) ? 1 : 0;
    const int g    = lane >> 3;
    const int c    = lane & 7;
    const int hd   = half * 4 + g;

    const float* ap = att + ((size_t)nq * HDh + hd) * 16;
    float l0 = ap[c], l1 = ap[c + 8];
    float m = fmaxf(l0, l1);
#pragma unroll
    for (int o = 4; o; o >>= 1) m = fmaxf(m, __shfl_xor_sync(FULLMASK, m, o, 8));
    float e0 = __expf(l0 - m), e1 = __expf(l1 - m);
    float s = e0 + e1;
#pragma unroll
    for (int o = 4; o; o >>= 1) s += __shfl_xor_sync(FULLMASK, s, o, 8);
    const float inv = 1.f / s;
    const float aw0 = e0 * inv, aw1 = e1 * inv;

    int   i00[2], i10[2], i01[2], i11[2];
    float w00[2], w10[2], w01[2], w11[2];
    const int nbase = n * LIN;
    const float* op = off + ((size_t)nq * HDh + hd) * 32;

#pragma unroll
    for (int sl = 0; sl < 2; sl++) {
        const int j = c + sl * 8;
        const int l = j >> 2;
        const int H  = shapes[2 * l + 0];
        const int W  = shapes[2 * l + 1];
        const int st = starts[l];
        const float rx = refp[((size_t)nq * Ll + l) * 2 + 0];
        const float ry = refp[((size_t)nq * Ll + l) * 2 + 1];
        const float2 o2 = *reinterpret_cast<const float2*>(op + j * 2);
        const float sx = fmaf(rx, (float)W, o2.x) - 0.5f;
        const float sy = fmaf(ry, (float)H, o2.y) - 0.5f;
        const float x0f = floorf(sx), y0f = floorf(sy);
        const int   x0 = (int)x0f,    y0 = (int)y0f;
        const float fx = sx - x0f,    fy = sy - y0f;
        const bool vx0 = (unsigned)x0       < (unsigned)W;
        const bool vx1 = (unsigned)(x0 + 1) < (unsigned)W;
        const bool vy0 = (unsigned)y0       < (unsigned)H;
        const bool vy1 = (unsigned)(y0 + 1) < (unsigned)H;
        const int cx0 = min(max(x0, 0), W - 1);
        const int cx1 = min(max(x0 + 1, 0), W - 1);
        const int cy0 = min(max(y0, 0), H - 1);
        const int cy1 = min(max(y0 + 1, 0), H - 1);
        const int b = nbase + st;
        i00[sl] = b + cy0 * W + cx0;
        i10[sl] = b + cy0 * W + cx1;
        i01[sl] = b + cy1 * W + cx0;
        i11[sl] = b + cy1 * W + cx1;
        const float aw = sl ? aw1 : aw0;
        w00[sl] = (vx0 & vy0) ? (1.f - fx) * (1.f - fy) * aw : 0.f;
        w10[sl] = (vx1 & vy0) ? fx * (1.f - fy) * aw : 0.f;
        w01[sl] = (vx0 & vy1) ? (1.f - fx) * fy * aw : 0.f;
        w11[sl] = (vx1 & vy1) ? fx * fy * aw : 0.f;
    }

    const float* vbase = value + hd * Dd + c * 4;
    float4 acc = make_float4(0.f, 0.f, 0.f, 0.f);

#pragma unroll
    for (int j = 0; j < 16; j++) {
        const int sl = j >> 3;
        const int sc = j & 7;
        const int   p00 = __shfl_sync(FULLMASK, i00[sl], sc, 8);
        const int   p10 = __shfl_sync(FULLMASK, i10[sl], sc, 8);
        const int   p01 = __shfl_sync(FULLMASK, i01[sl], sc, 8);
        const int   p11 = __shfl_sync(FULLMASK, i11[sl], sc, 8);
        const float q00 = __shfl_sync(FULLMASK, w00[sl], sc, 8);
        const float q10 = __shfl_sync(FULLMASK, w10[sl], sc, 8);
        const float q01 = __shfl_sync(FULLMASK, w01[sl], sc, 8);
        const float q11 = __shfl_sync(FULLMASK, w11[sl], sc, 8);

        float4 v;
        v = *reinterpret_cast<const float4*>(vbase + (size_t)p00 * CC);
        acc.x = fmaf(q00, v.x, acc.x); acc.y = fmaf(q00, v.y, acc.y);
        acc.z = fmaf(q00, v.z, acc.z); acc.w = fmaf(q00, v.w, acc.w);
        v = *reinterpret_cast<const float4*>(vbase + (size_t)p10 * CC);
        acc.x = fmaf(q10, v.x, acc.x); acc.y = fmaf(q10, v.y, acc.y);
        acc.z = fmaf(q10, v.z, acc.z); acc.w = fmaf(q10, v.w, acc.w);
        v = *reinterpret_cast<const float4*>(vbase + (size_t)p01 * CC);
        acc.x = fmaf(q01, v.x, acc.x); acc.y = fmaf(q01, v.y, acc.y);
        acc.z = fmaf(q01, v.z, acc.z); acc.w = fmaf(q01, v.w, acc.w);
        v = *reinterpret_cast<const float4*>(vbase + (size_t)p11 * CC);
        acc.x = fmaf(q11, v.x, acc.x); acc.y = fmaf(q11, v.y, acc.y);
        acc.z = fmaf(q11, v.z, acc.z); acc.w = fmaf(q11, v.w, acc.w);
    }

    *reinterpret_cast<float4*>(mid + (size_t)nq * CC + hd * Dd + c * 4) = acc;
}

// ---------------------------------------------------------------------------
// Launch
// ---------------------------------------------------------------------------
extern "C" void kernel_launch(void* const* d_in, const int* in_sizes, int n_in,
                              void* d_out, int out_size)
{
    const float* query  = (const float*)d_in[0];
    const float* refp   = (const float*)d_in[1];
    const float* inflat = (const float*)d_in[2];
    const int*   shapes = (const int*)  d_in[3];
    const int*   starts = (const int*)  d_in[4];
    const float* Wv     = (const float*)d_in[5];
    const float* bv     = (const float*)d_in[6];
    const float* Woff   = (const float*)d_in[7];
    const float* boff   = (const float*)d_in[8];
    const float* Watt   = (const float*)d_in[9];
    const float* batt   = (const float*)d_in[10];
    const float* Wout   = (const float*)d_in[11];
    const float* bout   = (const float*)d_in[12];
    float* out = (float*)d_out;

    void *pv, *po, *pa, *pm;
    cudaGetSymbolAddress(&pv, g_value);
    cudaGetSymbolAddress(&po, g_off);
    cudaGetSymbolAddress(&pa, g_att);
    cudaGetSymbolAddress(&pm, g_mid);
    float* gv = (float*)pv;
    float* go = (float*)po;
    float* ga = (float*)pa;
    float* gm = (float*)pm;

    const int M  = NN * LQn;          // 35642
    const int MB = (M + GBM - 1) / GBM;
    dim3 blk(256);

    // 1. value = input_flatten @ Wv + bv   [M, 256]
    gemm_bf16x3<<<dim3(256 / GBN, MB), blk>>>(inflat, Wv, bv, gv, M, 256, CC);
    // 2. offsets = query @ Woff + boff     [M, 256]
    gemm_bf16x3<<<dim3(256 / GBN, MB), blk>>>(query, Woff, boff, go, M, 256, CC);
    // 3. att logits = query @ Watt + batt  [M, 128]
    gemm_bf16x3<<<dim3(128 / GBN, MB), blk>>>(query, Watt, batt, ga, M, 128, CC);
    // 4. deformable sampling -> g_mid
    {
        const int totalWarps = NN * LQn * 2;
        dim3 grid((totalWarps + 7) / 8);
        msda_sample2<<<grid, blk>>>(gv, go, ga, refp, shapes, starts, gm);
    }
    // 5. out = g_mid @ Wout + bout         [M, 256]
    gemm_bf16x3<<<dim3(256 / GBN, MB), blk>>>(gm, Wout, bout, out, M, CC, CC);
}

// round 14
// speedup vs baseline: 2.8441x; 1.6338x over previous
#include <cuda_runtime.h>
#include <cuda_bf16.h>
#include <cstdint>

// Problem constants (fixed by the dataset)
#define NN   2
#define LQn  17821
#define CC   256
#define HDh  8
#define Ll   4
#define Pp   4
#define Dd   32
#define LIN  17821

#define FULLMASK 0xffffffffu

// Scratch (device globals; no allocation allowed)
__device__ float g_value[(size_t)NN * LIN * CC];
__device__ float g_off  [(size_t)NN * LQn * 256];
__device__ float g_att  [(size_t)NN * LQn * 128];
__device__ float g_mid  [(size_t)NN * LQn * CC];

// ---------------------------------------------------------------------------
// bf16x3 split-precision GEMM on tensor cores, software-pipelined.
//   C[M,N] = A[M,K] @ B[K,N] + bias[N].
//   a = hi + lo (bf16 each); C = Ahi*Bhi + Ahi*Blo + Alo*Bhi.
//   Next k-tile's global loads are prefetched into registers right after the
//   staging barrier, overlapping LDG latency with fragment loads + MMA.
// ---------------------------------------------------------------------------
#define GBM 128
#define GBN 128
#define GBK 16
#define AS_STRIDE 12         // conflict-free A frag LDS (verified: 12g+tig bijective mod 32)
#define BS_STRIDE (GBN + 8)  // conflict-free B frag LDS (verified: 8(tig+j)+g bijective mod 32)

__device__ __forceinline__ unsigned pack_bf2(__nv_bfloat16 a, __nv_bfloat16 b) {
    __nv_bfloat162 t = __halves2bfloat162(a, b);
    return *reinterpret_cast<unsigned*>(&t);
}

__device__ __forceinline__ void split_f32(float x, __nv_bfloat16& hi, __nv_bfloat16& lo) {
    hi = __float2bfloat16_rn(x);
    lo = __float2bfloat16_rn(x - __bfloat162float(hi));
}

__device__ __forceinline__ void mma_bf16(float* c, const unsigned* a, const unsigned* b) {
    asm volatile(
        "mma.sync.aligned.m16n8k16.row.col.f32.bf16.bf16.f32 "
        "{%0,%1,%2,%3}, {%4,%5,%6,%7}, {%8,%9}, {%0,%1,%2,%3};\n"
        : "+f"(c[0]), "+f"(c[1]), "+f"(c[2]), "+f"(c[3])
        : "r"(a[0]), "r"(a[1]), "r"(a[2]), "r"(a[3]), "r"(b[0]), "r"(b[1]));
}

__global__ __launch_bounds__(256) void gemm_bf16x3(
    const float* __restrict__ A, const float* __restrict__ B,
    const float* __restrict__ bias, float* __restrict__ C,
    int M, int N, int K)
{
    __shared__ unsigned AsH[GBM * AS_STRIDE];
    __shared__ unsigned AsL[GBM * AS_STRIDE];
    __shared__ unsigned BsH[(GBK / 2) * BS_STRIDE];
    __shared__ unsigned BsL[(GBK / 2) * BS_STRIDE];

    const int tid  = threadIdx.x;
    const int lane = tid & 31;
    const int warp = tid >> 5;
    const int g    = lane >> 2;
    const int tig  = lane & 3;
    const int wm   = warp >> 1;
    const int wn   = warp & 1;

    const int row0 = blockIdx.y * GBM;
    const int col0 = blockIdx.x * GBN;

    const int ar   = tid >> 1;            // 0..127
    const int acs  = (tid & 1) * 8;       // 0 or 8
    const int bk2  = tid >> 5;            // 0..7
    const int bnw  = (tid & 31) * 4;      // 0..124

    const bool aInM = (row0 + ar < M);
    const float* ApBase = A + (size_t)(row0 + ar) * K + acs;
    const float* BpBase = B + (size_t)(2 * bk2) * N + col0 + bnw;

    float acc[2][8][4];
#pragma unroll
    for (int i = 0; i < 2; i++)
#pragma unroll
        for (int j = 0; j < 8; j++)
#pragma unroll
            for (int r = 0; r < 4; r++) acc[i][j][r] = 0.f;

    // ---- prologue: load k-tile 0 into registers ----
    float4 pa0 = make_float4(0.f, 0.f, 0.f, 0.f);
    float4 pa1 = make_float4(0.f, 0.f, 0.f, 0.f);
    float4 pb0, pb1;
    if (aInM) {
        pa0 = *reinterpret_cast<const float4*>(ApBase);
        pa1 = *reinterpret_cast<const float4*>(ApBase + 4);
    }
    pb0 = *reinterpret_cast<const float4*>(BpBase);
    pb1 = *reinterpret_cast<const float4*>(BpBase + N);

    for (int k0 = 0; k0 < K; k0 += GBK) {
        // ---- split prefetched regs -> smem ----
        {
            __nv_bfloat16 h[8], l[8];
            split_f32(pa0.x, h[0], l[0]); split_f32(pa0.y, h[1], l[1]);
            split_f32(pa0.z, h[2], l[2]); split_f32(pa0.w, h[3], l[3]);
            split_f32(pa1.x, h[4], l[4]); split_f32(pa1.y, h[5], l[5]);
            split_f32(pa1.z, h[6], l[6]); split_f32(pa1.w, h[7], l[7]);
            uint4 uh = make_uint4(pack_bf2(h[0], h[1]), pack_bf2(h[2], h[3]),
                                  pack_bf2(h[4], h[5]), pack_bf2(h[6], h[7]));
            uint4 ul = make_uint4(pack_bf2(l[0], l[1]), pack_bf2(l[2], l[3]),
                                  pack_bf2(l[4], l[5]), pack_bf2(l[6], l[7]));
            const int w = ar * AS_STRIDE + (acs >> 1);
            *reinterpret_cast<uint4*>(&AsH[w]) = uh;
            *reinterpret_cast<uint4*>(&AsL[w]) = ul;
        }
        {
            __nv_bfloat16 h0[4], l0[4], h1[4], l1[4];
            split_f32(pb0.x, h0[0], l0[0]); split_f32(pb0.y, h0[1], l0[1]);
            split_f32(pb0.z, h0[2], l0[2]); split_f32(pb0.w, h0[3], l0[3]);
            split_f32(pb1.x, h1[0], l1[0]); split_f32(pb1.y, h1[1], l1[1]);
            split_f32(pb1.z, h1[2], l1[2]); split_f32(pb1.w, h1[3], l1[3]);
            uint4 uh = make_uint4(pack_bf2(h0[0], h1[0]), pack_bf2(h0[1], h1[1]),
                                  pack_bf2(h0[2], h1[2]), pack_bf2(h0[3], h1[3]));
            uint4 ul = make_uint4(pack_bf2(l0[0], l1[0]), pack_bf2(l0[1], l1[1]),
                                  pack_bf2(l0[2], l1[2]), pack_bf2(l0[3], l1[3]));
            const int w = bk2 * BS_STRIDE + bnw;
            *reinterpret_cast<uint4*>(&BsH[w]) = uh;
            *reinterpret_cast<uint4*>(&BsL[w]) = ul;
        }
        __syncthreads();

        // ---- prefetch next k-tile (overlaps with frag loads + MMA below) ----
        const int kn = k0 + GBK;
        if (kn < K) {
            if (aInM) {
                pa0 = *reinterpret_cast<const float4*>(ApBase + kn);
                pa1 = *reinterpret_cast<const float4*>(ApBase + kn + 4);
            }
            pb0 = *reinterpret_cast<const float4*>(BpBase + (size_t)kn * N);
            pb1 = *reinterpret_cast<const float4*>(BpBase + (size_t)(kn + 1) * N);
        }

        // ---- fragments + MMA ----
        unsigned aH[2][4], aL[2][4];
#pragma unroll
        for (int i = 0; i < 2; i++) {
            const int r0i = (wm * 32 + i * 16 + g) * AS_STRIDE;
            const int r1i = (wm * 32 + i * 16 + 8 + g) * AS_STRIDE;
            aH[i][0] = AsH[r0i + tig];     aH[i][1] = AsH[r1i + tig];
            aH[i][2] = AsH[r0i + tig + 4]; aH[i][3] = AsH[r1i + tig + 4];
            aL[i][0] = AsL[r0i + tig];     aL[i][1] = AsL[r1i + tig];
            aL[i][2] = AsL[r0i + tig + 4]; aL[i][3] = AsL[r1i + tig + 4];
        }
#pragma unroll
        for (int j = 0; j < 8; j++) {
            const int bc = wn * 64 + j * 8 + g;
            unsigned bH[2], bL[2];
            bH[0] = BsH[tig * BS_STRIDE + bc];
            bH[1] = BsH[(tig + 4) * BS_STRIDE + bc];
            bL[0] = BsL[tig * BS_STRIDE + bc];
            bL[1] = BsL[(tig + 4) * BS_STRIDE + bc];
#pragma unroll
            for (int i = 0; i < 2; i++) {
                mma_bf16(acc[i][j], aH[i], bH);
                mma_bf16(acc[i][j], aH[i], bL);
                mma_bf16(acc[i][j], aL[i], bH);
            }
        }
        __syncthreads();
    }

    // ---- epilogue: add bias, store fp32 ----
#pragma unroll
    for (int i = 0; i < 2; i++) {
#pragma unroll
        for (int j = 0; j < 8; j++) {
            const int col = col0 + wn * 64 + j * 8 + 2 * tig;
            const float b0 = bias[col], b1 = bias[col + 1];
            const int r0i = row0 + wm * 32 + i * 16 + g;
            if (r0i < M) {
                float2 v = make_float2(acc[i][j][0] + b0, acc[i][j][1] + b1);
                *reinterpret_cast<float2*>(C + (size_t)r0i * N + col) = v;
            }
            if (r0i + 8 < M) {
                float2 v = make_float2(acc[i][j][2] + b0, acc[i][j][3] + b1);
                *reinterpret_cast<float2*>(C + (size_t)(r0i + 8) * N + col) = v;
            }
        }
    }
}

// ---------------------------------------------------------------------------
// Deformable sampling (round-2 winner, unchanged): one warp per (n, lq, head-half)
// ---------------------------------------------------------------------------
__global__ __launch_bounds__(256) void msda_sample2(
    const float* __restrict__ value,
    const float* __restrict__ off,
    const float* __restrict__ att,
    const float* __restrict__ refp,
    const int*   __restrict__ shapes,
    const int*   __restrict__ starts,
    float* __restrict__ mid)
{
    const int lane = threadIdx.x & 31;
    const int wid  = blockIdx.x * (blockDim.x >> 5) + (threadIdx.x >> 5);
    if (wid >= NN * LQn * 2) return;

    const int nq   = wid >> 1;
    const int half = wid & 1;
    const int n    = (nq >= LQn) ? 1 : 0;
    const int g    = lane >> 3;
    const int c    = lane & 7;
    const int hd   = half * 4 + g;

    const float* ap = att + ((size_t)nq * HDh + hd) * 16;
    float l0 = ap[c], l1 = ap[c + 8];
    float m = fmaxf(l0, l1);
#pragma unroll
    for (int o = 4; o; o >>= 1) m = fmaxf(m, __shfl_xor_sync(FULLMASK, m, o, 8));
    float e0 = __expf(l0 - m), e1 = __expf(l1 - m);
    float s = e0 + e1;
#pragma unroll
    for (int o = 4; o; o >>= 1) s += __shfl_xor_sync(FULLMASK, s, o, 8);
    const float inv = 1.f / s;
    const float aw0 = e0 * inv, aw1 = e1 * inv;

    int   i00[2], i10[2], i01[2], i11[2];
    float w00[2], w10[2], w01[2], w11[2];
    const int nbase = n * LIN;
    const float* op = off + ((size_t)nq * HDh + hd) * 32;

#pragma unroll
    for (int sl = 0; sl < 2; sl++) {
        const int j = c + sl * 8;
        const int l = j >> 2;
        const int H  = shapes[2 * l + 0];
        const int W  = shapes[2 * l + 1];
        const int st = starts[l];
        const float rx = refp[((size_t)nq * Ll + l) * 2 + 0];
        const float ry = refp[((size_t)nq * Ll + l) * 2 + 1];
        const float2 o2 = *reinterpret_cast<const float2*>(op + j * 2);
        const float sx = fmaf(rx, (float)W, o2.x) - 0.5f;
        const float sy = fmaf(ry, (float)H, o2.y) - 0.5f;
        const float x0f = floorf(sx), y0f = floorf(sy);
        const int   x0 = (int)x0f,    y0 = (int)y0f;
        const float fx = sx - x0f,    fy = sy - y0f;
        const bool vx0 = (unsigned)x0       < (unsigned)W;
        const bool vx1 = (unsigned)(x0 + 1) < (unsigned)W;
        const bool vy0 = (unsigned)y0       < (unsigned)H;
        const bool vy1 = (unsigned)(y0 + 1) < (unsigned)H;
        const int cx0 = min(max(x0, 0), W - 1);
        const int cx1 = min(max(x0 + 1, 0), W - 1);
        const int cy0 = min(max(y0, 0), H - 1);
        const int cy1 = min(max(y0 + 1, 0), H - 1);
        const int b = nbase + st;
        i00[sl] = b + cy0 * W + cx0;
        i10[sl] = b + cy0 * W + cx1;
        i01[sl] = b + cy1 * W + cx0;
        i11[sl] = b + cy1 * W + cx1;
        const float aw = sl ? aw1 : aw0;
        w00[sl] = (vx0 & vy0) ? (1.f - fx) * (1.f - fy) * aw : 0.f;
        w10[sl] = (vx1 & vy0) ? fx * (1.f - fy) * aw : 0.f;
        w01[sl] = (vx0 & vy1) ? (1.f - fx) * fy * aw : 0.f;
        w11[sl] = (vx1 & vy1) ? fx * fy * aw : 0.f;
    }

    const float* vbase = value + hd * Dd + c * 4;
    float4 acc = make_float4(0.f, 0.f, 0.f, 0.f);

#pragma unroll
    for (int j = 0; j < 16; j++) {
        const int sl = j >> 3;
        const int sc = j & 7;
        const int   p00 = __shfl_sync(FULLMASK, i00[sl], sc, 8);
        const int   p10 = __shfl_sync(FULLMASK, i10[sl], sc, 8);
        const int   p01 = __shfl_sync(FULLMASK, i01[sl], sc, 8);
        const int   p11 = __shfl_sync(FULLMASK, i11[sl], sc, 8);
        const float q00 = __shfl_sync(FULLMASK, w00[sl], sc, 8);
        const float q10 = __shfl_sync(FULLMASK, w10[sl], sc, 8);
        const float q01 = __shfl_sync(FULLMASK, w01[sl], sc, 8);
        const float q11 = __shfl_sync(FULLMASK, w11[sl], sc, 8);

        float4 v;
        v = *reinterpret_cast<const float4*>(vbase + (size_t)p00 * CC);
        acc.x = fmaf(q00, v.x, acc.x); acc.y = fmaf(q00, v.y, acc.y);
        acc.z = fmaf(q00, v.z, acc.z); acc.w = fmaf(q00, v.w, acc.w);
        v = *reinterpret_cast<const float4*>(vbase + (size_t)p10 * CC);
        acc.x = fmaf(q10, v.x, acc.x); acc.y = fmaf(q10, v.y, acc.y);
        acc.z = fmaf(q10, v.z, acc.z); acc.w = fmaf(q10, v.w, acc.w);
        v = *reinterpret_cast<const float4*>(vbase + (size_t)p01 * CC);
        acc.x = fmaf(q01, v.x, acc.x); acc.y = fmaf(q01, v.y, acc.y);
        acc.z = fmaf(q01, v.z, acc.z); acc.w = fmaf(q01, v.w, acc.w);
        v = *reinterpret_cast<const float4*>(vbase + (size_t)p11 * CC);
        acc.x = fmaf(q11, v.x, acc.x); acc.y = fmaf(q11, v.y, acc.y);
        acc.z = fmaf(q11, v.z, acc.z); acc.w = fmaf(q11, v.w, acc.w);
    }

    *reinterpret_cast<float4*>(mid + (size_t)nq * CC + hd * Dd + c * 4) = acc;
}

// ---------------------------------------------------------------------------
// Launch
// ---------------------------------------------------------------------------
extern "C" void kernel_launch(void* const* d_in, const int* in_sizes, int n_in,
                              void* d_out, int out_size)
{
    const float* query  = (const float*)d_in[0];
    const float* refp   = (const float*)d_in[1];
    const float* inflat = (const float*)d_in[2];
    const int*   shapes = (const int*)  d_in[3];
    const int*   starts = (const int*)  d_in[4];
    const float* Wv     = (const float*)d_in[5];
    const float* bv     = (const float*)d_in[6];
    const float* Woff   = (const float*)d_in[7];
    const float* boff   = (const float*)d_in[8];
    const float* Watt   = (const float*)d_in[9];
    const float* batt   = (const float*)d_in[10];
    const float* Wout   = (const float*)d_in[11];
    const float* bout   = (const float*)d_in[12];
    float* out = (float*)d_out;

    void *pv, *po, *pa, *pm;
    cudaGetSymbolAddress(&pv, g_value);
    cudaGetSymbolAddress(&po, g_off);
    cudaGetSymbolAddress(&pa, g_att);
    cudaGetSymbolAddress(&pm, g_mid);
    float* gv = (float*)pv;
    float* go = (float*)po;
    float* ga = (float*)pa;
    float* gm = (float*)pm;

    const int M  = NN * LQn;          // 35642
    const int MB = (M + GBM - 1) / GBM;
    dim3 blk(256);

    // 1. value = input_flatten @ Wv + bv   [M, 256]
    gemm_bf16x3<<<dim3(256 / GBN, MB), blk>>>(inflat, Wv, bv, gv, M, 256, CC);
    // 2. offsets = query @ Woff + boff     [M, 256]
    gemm_bf16x3<<<dim3(256 / GBN, MB), blk>>>(query, Woff, boff, go, M, 256, CC);
    // 3. att logits = query @ Watt + batt  [M, 128]
    gemm_bf16x3<<<dim3(128 / GBN, MB), blk>>>(query, Watt, batt, ga, M, 128, CC);
    // 4. deformable sampling -> g_mid
    {
        const int totalWarps = NN * LQn * 2;
        dim3 grid((totalWarps + 7) / 8);
        msda_sample2<<<grid, blk>>>(gv, go, ga, refp, shapes, starts, gm);
    }
    // 5. out = g_mid @ Wout + bout         [M, 256]
    gemm_bf16x3<<<dim3(256 / GBN, MB), blk>>>(gm, Wout, bout, out, M, CC, CC);
}